// round 3
// baseline (speedup 1.0000x reference)
#include <cuda_runtime.h>
#include <cuda_bf16.h>
#include <cstdint>

#define LAT 2048

// Scratch: M = W^T @ cos_basis  (2048 x 2048 f32, 16.8 MB)
__device__ float g_M[(size_t)LAT * LAT];
// Global max accumulator, monotonic-unsigned encoding of float
__device__ unsigned g_max_bits;

__device__ __forceinline__ unsigned fenc(float f) {
    unsigned u = __float_as_uint(f);
    return (u & 0x80000000u) ? ~u : (u | 0x80000000u);
}
__device__ __forceinline__ float fdec(unsigned u) {
    unsigned b = (u & 0x80000000u) ? (u ^ 0x80000000u) : ~u;
    return __uint_as_float(b);
}

__global__ void reset_max_kernel() { g_max_bits = 0u; }

// ---------------------------------------------------------------------------
// GEMM1: M[m][n] = sum_k W[k][m] * C[k][n]     (both operands K-major!)
//   W: (K x 2048) row-major (K = n_freq = 2074), C: (K x 2048) row-major
//   Tile: BM=BN=128, BK=8, 256 threads, 8x8 accum per thread.
//   Tile loads are contiguous 128-float rows -> fully coalesced float4.
// ---------------------------------------------------------------------------
__global__ __launch_bounds__(256, 2)
void gemm1_ktkt(const float* __restrict__ A,   // W
                const float* __restrict__ B,   // cos_basis
                int K)
{
    __shared__ float As[8][128];
    __shared__ float Bs[8][128];

    const int tid = threadIdx.x;
    const int m0 = blockIdx.y * 128;
    const int n0 = blockIdx.x * 128;
    const int ty = tid >> 4;          // 0..15
    const int tx = tid & 15;          // 0..15

    // loader mapping: 256 float4 per tile -> one per thread
    const int lr = tid >> 5;          // k-row 0..7
    const int lc = (tid & 31) << 2;   // col 0..124 step 4

    float acc[8][8];
#pragma unroll
    for (int i = 0; i < 8; i++)
#pragma unroll
        for (int j = 0; j < 8; j++) acc[i][j] = 0.f;

    for (int k0 = 0; k0 < K; k0 += 8) {
        float4 av = make_float4(0.f, 0.f, 0.f, 0.f);
        float4 bv = make_float4(0.f, 0.f, 0.f, 0.f);
        const int k = k0 + lr;
        if (k < K) {
            av = *(const float4*)(A + (size_t)k * LAT + m0 + lc);
            bv = *(const float4*)(B + (size_t)k * LAT + n0 + lc);
        }
        __syncthreads();
        *(float4*)&As[lr][lc] = av;
        *(float4*)&Bs[lr][lc] = bv;
        __syncthreads();

#pragma unroll
        for (int kk = 0; kk < 8; kk++) {
            float a[8], b[8];
#pragma unroll
            for (int i = 0; i < 8; i++) a[i] = As[kk][ty * 8 + i];
#pragma unroll
            for (int j = 0; j < 8; j++) b[j] = Bs[kk][tx * 8 + j];
#pragma unroll
            for (int i = 0; i < 8; i++)
#pragma unroll
                for (int j = 0; j < 8; j++)
                    acc[i][j] = fmaf(a[i], b[j], acc[i][j]);
        }
    }

#pragma unroll
    for (int i = 0; i < 8; i++) {
        const size_t row = (size_t)(m0 + ty * 8 + i) * LAT + n0 + tx * 8;
#pragma unroll
        for (int j = 0; j < 8; j += 4)
            *(float4*)&g_M[row + j] =
                make_float4(acc[i][j], acc[i][j + 1], acc[i][j + 2], acc[i][j + 3]);
    }
}

// ---------------------------------------------------------------------------
// GEMM2: out[m][n] = sum_k x[m][k] * M[k][n]   (K = 2048 exact)
//   x row-major (BATCH x 2048): A-tile load is transposed into shared.
//   Epilogue: block max -> encoded atomicMax into g_max_bits.
// ---------------------------------------------------------------------------
__global__ __launch_bounds__(256, 2)
void gemm2_nn(const float* __restrict__ A,   // x
              float* __restrict__ C)         // out (unscaled)
{
    __shared__ float As[8][128];
    __shared__ float Bs[8][128];

    const int tid = threadIdx.x;
    const int m0 = blockIdx.y * 128;
    const int n0 = blockIdx.x * 128;
    const int ty = tid >> 4;
    const int tx = tid & 15;

    // A loader: 128 m-rows x 8 k: thread t loads float4 along k
    const int am = tid >> 1;            // 0..127
    const int ak = (tid & 1) << 2;      // 0 or 4
    // B loader: standard row loader
    const int lr = tid >> 5;
    const int lc = (tid & 31) << 2;

    float acc[8][8];
#pragma unroll
    for (int i = 0; i < 8; i++)
#pragma unroll
        for (int j = 0; j < 8; j++) acc[i][j] = 0.f;

    for (int k0 = 0; k0 < LAT; k0 += 8) {
        const float4 av = *(const float4*)(A + (size_t)(m0 + am) * LAT + k0 + ak);
        const float4 bv = *(const float4*)(g_M + (size_t)(k0 + lr) * LAT + n0 + lc);
        __syncthreads();
        As[ak + 0][am] = av.x;
        As[ak + 1][am] = av.y;
        As[ak + 2][am] = av.z;
        As[ak + 3][am] = av.w;
        *(float4*)&Bs[lr][lc] = bv;
        __syncthreads();

#pragma unroll
        for (int kk = 0; kk < 8; kk++) {
            float a[8], b[8];
#pragma unroll
            for (int i = 0; i < 8; i++) a[i] = As[kk][ty * 8 + i];
#pragma unroll
            for (int j = 0; j < 8; j++) b[j] = Bs[kk][tx * 8 + j];
#pragma unroll
            for (int i = 0; i < 8; i++)
#pragma unroll
                for (int j = 0; j < 8; j++)
                    acc[i][j] = fmaf(a[i], b[j], acc[i][j]);
        }
    }

    // write unscaled result
    float lmax = -3.402823466e+38f;
#pragma unroll
    for (int i = 0; i < 8; i++) {
        const size_t row = (size_t)(m0 + ty * 8 + i) * LAT + n0 + tx * 8;
#pragma unroll
        for (int j = 0; j < 8; j += 4)
            *(float4*)&C[row + j] =
                make_float4(acc[i][j], acc[i][j + 1], acc[i][j + 2], acc[i][j + 3]);
#pragma unroll
        for (int j = 0; j < 8; j++) lmax = fmaxf(lmax, acc[i][j]);
    }

    // block max reduction
#pragma unroll
    for (int off = 16; off > 0; off >>= 1)
        lmax = fmaxf(lmax, __shfl_xor_sync(0xFFFFFFFFu, lmax, off));
    __shared__ float wmax[8];
    if ((tid & 31) == 0) wmax[tid >> 5] = lmax;
    __syncthreads();
    if (tid == 0) {
        float m = wmax[0];
#pragma unroll
        for (int w = 1; w < 8; w++) m = fmaxf(m, wmax[w]);
        atomicMax(&g_max_bits, fenc(m));
    }
}

// ---------------------------------------------------------------------------
// Scale: out *= 1/max
// ---------------------------------------------------------------------------
__global__ void scale_kernel(float* __restrict__ out, int n4)
{
    const float inv = 1.0f / fdec(g_max_bits);
    const int i = blockIdx.x * blockDim.x + threadIdx.x;
    if (i < n4) {
        float4 v = ((float4*)out)[i];
        v.x *= inv; v.y *= inv; v.z *= inv; v.w *= inv;
        ((float4*)out)[i] = v;
    }
}

extern "C" void kernel_launch(void* const* d_in, const int* in_sizes, int n_in,
                              void* d_out, int out_size)
{
    const float* x = (const float*)d_in[0];          // (B, 2048)
    const float* W = (const float*)d_in[1];          // (NF, 2048)
    const float* C = (const float*)d_in[2];          // (NF, 2048)
    float* out = (float*)d_out;

    const int B  = in_sizes[0] / LAT;                // 4096
    const int NF = in_sizes[1] / LAT;                // 2074

    reset_max_kernel<<<1, 1>>>();

    // GEMM1: M = W^T @ C   (2048 x 2048, K = NF)
    gemm1_ktkt<<<dim3(LAT / 128, LAT / 128), 256>>>(W, C, NF);

    // GEMM2: out = x @ M  + fused global-max
    gemm2_nn<<<dim3(LAT / 128, B / 128), 256>>>(x, out);

    // out /= max
    const int n4 = out_size / 4;
    scale_kernel<<<(n4 + 255) / 256, 256>>>(out, n4);
}

// round 5
// speedup vs baseline: 2.0417x; 2.0417x over previous
#include <cuda_runtime.h>
#include <cuda_bf16.h>
#include <cstdint>

#define LAT   2048
#define MAXB  4096
#define K1PAD 2112            // n_freq (2074) padded to multiple of 32

// ---------------------------------------------------------------------------
// Scratch (static __device__ — no allocations allowed)
// ---------------------------------------------------------------------------
__device__ __nv_bfloat16 g_Wt_hi[(size_t)LAT * K1PAD];
__device__ __nv_bfloat16 g_Wt_lo[(size_t)LAT * K1PAD];
__device__ __nv_bfloat16 g_Ct_hi[(size_t)LAT * K1PAD];
__device__ __nv_bfloat16 g_Ct_lo[(size_t)LAT * K1PAD];
__device__ __nv_bfloat16 g_Mt_hi[(size_t)LAT * LAT];   // M^T rows n, K-major over m
__device__ __nv_bfloat16 g_Mt_lo[(size_t)LAT * LAT];
__device__ __nv_bfloat16 g_x_hi[(size_t)MAXB * LAT];
__device__ __nv_bfloat16 g_x_lo[(size_t)MAXB * LAT];
__device__ unsigned g_max_bits;

// ---------------------------------------------------------------------------
// Helpers
// ---------------------------------------------------------------------------
__device__ __forceinline__ unsigned fenc(float f) {
    unsigned u = __float_as_uint(f);
    return (u & 0x80000000u) ? ~u : (u | 0x80000000u);
}
__device__ __forceinline__ float fdec(unsigned u) {
    unsigned b = (u & 0x80000000u) ? (u ^ 0x80000000u) : ~u;
    return __uint_as_float(b);
}
__device__ __forceinline__ void split1(float v, __nv_bfloat16& h, __nv_bfloat16& l) {
    h = __float2bfloat16(v);
    l = __float2bfloat16(v - __bfloat162float(h));
}
__device__ __forceinline__ uint32_t smem_u32(const void* p) {
    return (uint32_t)__cvta_generic_to_shared(p);
}
__device__ __forceinline__ void cpasync16(uint32_t dst, const void* src) {
    asm volatile("cp.async.cg.shared.global [%0], [%1], 16;" :: "r"(dst), "l"(src));
}
#define CP_COMMIT() asm volatile("cp.async.commit_group;" ::: "memory")
#define CP_WAIT1()  asm volatile("cp.async.wait_group 1;" ::: "memory")

__device__ __forceinline__ void ldsm4(uint32_t* r, uint32_t addr) {
    asm volatile("ldmatrix.sync.aligned.m8n8.x4.shared.b16 {%0,%1,%2,%3}, [%4];"
                 : "=r"(r[0]), "=r"(r[1]), "=r"(r[2]), "=r"(r[3]) : "r"(addr));
}
__device__ __forceinline__ void mma16816(float* c, const uint32_t* a, const uint32_t* b) {
    asm volatile("mma.sync.aligned.m16n8k16.row.col.f32.bf16.bf16.f32 "
                 "{%0,%1,%2,%3}, {%4,%5,%6,%7}, {%8,%9}, {%0,%1,%2,%3};"
                 : "+f"(c[0]), "+f"(c[1]), "+f"(c[2]), "+f"(c[3])
                 : "r"(a[0]), "r"(a[1]), "r"(a[2]), "r"(a[3]), "r"(b[0]), "r"(b[1]));
}

// smem tile geometry: 128 rows x 32 bf16, rows padded to 80 B (conflict-free LDSM)
#define ROWB        80
#define TILE_B      (128 * ROWB)      // 10240
#define STAGE_B     (4 * TILE_B)      // 40960  (Ah, Al, Bh, Bl)
#define NSTAGE      3
#define SMEM_BYTES  (NSTAGE * STAGE_B)

// ---------------------------------------------------------------------------
// Prep kernels
// ---------------------------------------------------------------------------
__global__ void reset_max_kernel() { g_max_bits = 0u; }

// transpose + hi/lo split: src [K][2048] f32 -> dst [2048][K1PAD] bf16 (pad=0)
__global__ void transpose_split_kernel(const float* __restrict__ src, int K, int which)
{
    __shared__ float t[32][33];
    __nv_bfloat16* hi = which ? g_Ct_hi : g_Wt_hi;
    __nv_bfloat16* lo = which ? g_Ct_lo : g_Wt_lo;
    const int kb = blockIdx.y * 32;
    const int mb = blockIdx.x * 32;
    const int tx = threadIdx.x, ty = threadIdx.y;
#pragma unroll
    for (int r = ty; r < 32; r += 8) {
        const int k = kb + r;
        t[r][tx] = (k < K) ? src[(size_t)k * LAT + mb + tx] : 0.f;
    }
    __syncthreads();
#pragma unroll
    for (int r = ty; r < 32; r += 8) {
        const int m = mb + r;
        const int k = kb + tx;
        __nv_bfloat16 h, l;
        split1(t[tx][r], h, l);
        hi[(size_t)m * K1PAD + k] = h;
        lo[(size_t)m * K1PAD + k] = l;
    }
}

__global__ void split_x_kernel(const float* __restrict__ x, int n2)
{
    const int i = blockIdx.x * blockDim.x + threadIdx.x;
    if (i < n2) {
        const float2 v = ((const float2*)x)[i];
        __nv_bfloat16 h0, l0, h1, l1;
        split1(v.x, h0, l0);
        split1(v.y, h1, l1);
        __nv_bfloat162 hh; hh.x = h0; hh.y = h1;
        __nv_bfloat162 ll; ll.x = l0; ll.y = l1;
        ((__nv_bfloat162*)g_x_hi)[i] = hh;
        ((__nv_bfloat162*)g_x_lo)[i] = ll;
    }
}

// ---------------------------------------------------------------------------
// GEMM mainloop: acc[mt][nt][4] += sum_k A[arow][k] * B[brow][k]  (split bf16)
// 256 threads, 8 warps as 2(m) x 4(n); warp tile 64x32.
// ---------------------------------------------------------------------------
__device__ __forceinline__ void gemm_main(
    const __nv_bfloat16* __restrict__ Ah, const __nv_bfloat16* __restrict__ Al,
    const __nv_bfloat16* __restrict__ Bh, const __nv_bfloat16* __restrict__ Bl,
    int arow0, int brow0, int ldk, int nchunks,
    char* smem, float acc[4][4][4])
{
    const int tid = threadIdx.x;
    const int lane = tid & 31;
    const int w = tid >> 5;
    const int wm = w >> 2;            // 0..1
    const int wn = w & 3;             // 0..3
    const uint32_t sbase = smem_u32(smem);

#pragma unroll
    for (int mt = 0; mt < 4; mt++)
#pragma unroll
        for (int nt = 0; nt < 4; nt++)
#pragma unroll
            for (int q = 0; q < 4; q++) acc[mt][nt][q] = 0.f;

    // ---- global->shared loader mapping: thread covers 32B of one row ----
    const int lr = tid >> 1;                    // row 0..127
    const int lc0 = (tid & 1) * 2;              // 16B-chunk base (0 or 2)
    const __nv_bfloat16* ga[4];
    ga[0] = Ah + (size_t)(arow0 + lr) * ldk;
    ga[1] = Al + (size_t)(arow0 + lr) * ldk;
    ga[2] = Bh + (size_t)(brow0 + lr) * ldk;
    ga[3] = Bl + (size_t)(brow0 + lr) * ldk;
    const uint32_t sdst0 = sbase + lr * ROWB + lc0 * 16;

    // ---- ldmatrix lane offsets (within a tile) ----
    uint32_t aoff[2][4], boff[2][2];
#pragma unroll
    for (int ks = 0; ks < 2; ks++) {
#pragma unroll
        for (int mt = 0; mt < 4; mt++)
            aoff[ks][mt] = sbase + (uint32_t)((wm * 64 + mt * 16 + (lane & 15)) * ROWB
                                              + ks * 32 + (lane >> 4) * 16);
#pragma unroll
        for (int np = 0; np < 2; np++)
            boff[ks][np] = sbase + (uint32_t)((wn * 32 + np * 16 + (lane & 7) + (lane >> 4) * 8) * ROWB
                                              + ks * 32 + ((lane >> 3) & 1) * 16);
    }

#define LOAD_STAGE(c, s)                                                       \
    do {                                                                       \
        const size_t ke = (size_t)(c) * 32 + lc0 * 8;                          \
        const uint32_t d = sdst0 + (s) * STAGE_B;                              \
        _Pragma("unroll")                                                      \
        for (int t4 = 0; t4 < 4; t4++) {                                       \
            const char* srcp = (const char*)(ga[t4] + ke);                     \
            cpasync16(d + t4 * TILE_B, srcp);                                  \
            cpasync16(d + t4 * TILE_B + 16, srcp + 16);                        \
        }                                                                      \
    } while (0)

    LOAD_STAGE(0, 0); CP_COMMIT();
    LOAD_STAGE(1, 1); CP_COMMIT();

    uint32_t a[2][4][4], b[2][2][4];

    for (int c = 0; c < nchunks; ++c) {
        const int s = c % NSTAGE;
        CP_WAIT1();
        __syncthreads();
        const int nc = c + NSTAGE - 1;
        if (nc < nchunks) LOAD_STAGE(nc, nc % NSTAGE);
        CP_COMMIT();

        const uint32_t so = (uint32_t)(s * STAGE_B);

#define LDA(toff)                                                              \
        _Pragma("unroll")                                                      \
        for (int ks = 0; ks < 2; ks++)                                         \
            _Pragma("unroll")                                                  \
            for (int mt = 0; mt < 4; mt++)                                     \
                ldsm4(a[ks][mt], aoff[ks][mt] + so + (toff));
#define LDB(toff)                                                              \
        _Pragma("unroll")                                                      \
        for (int ks = 0; ks < 2; ks++)                                         \
            _Pragma("unroll")                                                  \
            for (int np = 0; np < 2; np++)                                     \
                ldsm4(b[ks][np], boff[ks][np] + so + (toff));
#define DOMMA()                                                                \
        _Pragma("unroll")                                                      \
        for (int ks = 0; ks < 2; ks++)                                         \
            _Pragma("unroll")                                                  \
            for (int mt = 0; mt < 4; mt++)                                     \
                _Pragma("unroll")                                              \
                for (int np = 0; np < 2; np++) {                               \
                    mma16816(acc[mt][np * 2 + 0], a[ks][mt], &b[ks][np][0]);   \
                    mma16816(acc[mt][np * 2 + 1], a[ks][mt], &b[ks][np][2]);   \
                }

        LDA(0);            LDB(2 * TILE_B);  DOMMA();   // Ah * Bh
        LDA(TILE_B);                         DOMMA();   // Al * Bh
        LDB(3 * TILE_B);   LDA(0);           DOMMA();   // Ah * Bl
#undef LDA
#undef LDB
#undef DOMMA
    }
#undef LOAD_STAGE
}

// ---------------------------------------------------------------------------
// GEMM1: Mt[n][m] = sum_k Ct[n][k] * Wt[m][k]; epilogue re-splits to bf16 hi/lo.
// ---------------------------------------------------------------------------
__global__ __launch_bounds__(256, 1) void gemm1_tc()
{
    extern __shared__ __align__(128) char smem[];
    float acc[4][4][4];
    gemm_main(g_Ct_hi, g_Ct_lo, g_Wt_hi, g_Wt_lo,
              blockIdx.y * 128, blockIdx.x * 128, K1PAD, K1PAD / 32, smem, acc);

    const int lane = threadIdx.x & 31;
    const int w = threadIdx.x >> 5;
    const int r0 = blockIdx.y * 128 + (w >> 2) * 64;
    const int c0 = blockIdx.x * 128 + (w & 3) * 32;

#pragma unroll
    for (int mt = 0; mt < 4; mt++) {
#pragma unroll
        for (int nt = 0; nt < 4; nt++) {
            const int col = c0 + nt * 8 + (lane & 3) * 2;
            const float* cc = acc[mt][nt];
#pragma unroll
            for (int h = 0; h < 2; h++) {
                const int r = r0 + mt * 16 + (lane >> 2) + h * 8;
                const size_t idx = (size_t)r * LAT + col;
                __nv_bfloat16 h0, l0, h1, l1;
                split1(cc[2 * h + 0], h0, l0);
                split1(cc[2 * h + 1], h1, l1);
                *(uint32_t*)(g_Mt_hi + idx) =
                    (uint32_t)__bfloat16_as_ushort(h0) | ((uint32_t)__bfloat16_as_ushort(h1) << 16);
                *(uint32_t*)(g_Mt_lo + idx) =
                    (uint32_t)__bfloat16_as_ushort(l0) | ((uint32_t)__bfloat16_as_ushort(l1) << 16);
            }
        }
    }
}

// ---------------------------------------------------------------------------
// GEMM2: out[b][n] = sum_m x[b][m] * Mt[n][m]; fused global max.
// ---------------------------------------------------------------------------
__global__ __launch_bounds__(256, 1) void gemm2_tc(float* __restrict__ out)
{
    extern __shared__ __align__(128) char smem[];
    float acc[4][4][4];
    gemm_main(g_x_hi, g_x_lo, g_Mt_hi, g_Mt_lo,
              blockIdx.y * 128, blockIdx.x * 128, LAT, LAT / 32, smem, acc);

    const int lane = threadIdx.x & 31;
    const int w = threadIdx.x >> 5;
    const int r0 = blockIdx.y * 128 + (w >> 2) * 64;
    const int c0 = blockIdx.x * 128 + (w & 3) * 32;

    float lmax = -3.402823466e+38f;
#pragma unroll
    for (int mt = 0; mt < 4; mt++) {
#pragma unroll
        for (int nt = 0; nt < 4; nt++) {
            const int col = c0 + nt * 8 + (lane & 3) * 2;
            const float* cc = acc[mt][nt];
#pragma unroll
            for (int h = 0; h < 2; h++) {
                const int r = r0 + mt * 16 + (lane >> 2) + h * 8;
                float2 v = make_float2(cc[2 * h + 0], cc[2 * h + 1]);
                lmax = fmaxf(lmax, fmaxf(v.x, v.y));
                *(float2*)(out + (size_t)r * LAT + col) = v;
            }
        }
    }

#pragma unroll
    for (int o = 16; o > 0; o >>= 1)
        lmax = fmaxf(lmax, __shfl_xor_sync(0xFFFFFFFFu, lmax, o));
    __shared__ float wmax[8];
    if (lane == 0) wmax[w] = lmax;
    __syncthreads();
    if (threadIdx.x == 0) {
        float m = wmax[0];
#pragma unroll
        for (int i = 1; i < 8; i++) m = fmaxf(m, wmax[i]);
        atomicMax(&g_max_bits, fenc(m));
    }
}

// ---------------------------------------------------------------------------
// out *= 1/max
// ---------------------------------------------------------------------------
__global__ void scale_kernel(float* __restrict__ out, int n4)
{
    const float inv = 1.0f / fdec(g_max_bits);
    const int i = blockIdx.x * blockDim.x + threadIdx.x;
    if (i < n4) {
        float4 v = ((float4*)out)[i];
        v.x *= inv; v.y *= inv; v.z *= inv; v.w *= inv;
        ((float4*)out)[i] = v;
    }
}

// ---------------------------------------------------------------------------
extern "C" void kernel_launch(void* const* d_in, const int* in_sizes, int n_in,
                              void* d_out, int out_size)
{
    const float* x = (const float*)d_in[0];   // (B, 2048)
    const float* W = (const float*)d_in[1];   // (NF, 2048)
    const float* C = (const float*)d_in[2];   // (NF, 2048)
    float* out = (float*)d_out;

    const int B  = in_sizes[0] / LAT;         // 4096
    const int NF = in_sizes[1] / LAT;         // 2074

    cudaFuncSetAttribute(gemm1_tc, cudaFuncAttributeMaxDynamicSharedMemorySize, SMEM_BYTES);
    cudaFuncSetAttribute(gemm2_tc, cudaFuncAttributeMaxDynamicSharedMemorySize, SMEM_BYTES);

    reset_max_kernel<<<1, 1>>>();

    dim3 tb(32, 8);
    transpose_split_kernel<<<dim3(LAT / 32, K1PAD / 32), tb>>>(W, NF, 0);
    transpose_split_kernel<<<dim3(LAT / 32, K1PAD / 32), tb>>>(C, NF, 1);
    const int n2 = B * LAT / 2;
    split_x_kernel<<<(n2 + 255) / 256, 256>>>(x, n2);

    // GEMM1: Mt = (W^T C)^T   (2048x2048, K = K1PAD)
    gemm1_tc<<<dim3(LAT / 128, LAT / 128), 256, SMEM_BYTES>>>();

    // GEMM2: out = x @ M + fused global max
    gemm2_tc<<<dim3(LAT / 128, B / 128), 256, SMEM_BYTES>>>(out);

    const int n4 = out_size / 4;
    scale_kernel<<<(n4 + 255) / 256, 256>>>(out, n4);
}

// round 9
// speedup vs baseline: 4.8780x; 2.3892x over previous
#include <cuda_runtime.h>
#include <cuda_fp16.h>
#include <cstdint>

#define LAT   2048
#define MAXB  4096
#define K1PAD 2112            // n_freq (2074) padded to multiple of 32

// ---------------------------------------------------------------------------
// Scratch (static __device__ — no allocations allowed)
// ---------------------------------------------------------------------------
__device__ __half g_Wt[(size_t)LAT * K1PAD];   // W^T, K-major (K = n_freq)
__device__ __half g_Ct[(size_t)LAT * K1PAD];   // C^T, K-major
__device__ __half g_Mt[(size_t)LAT * LAT];     // M^T rows n, K-major over m
__device__ __half g_x [(size_t)MAXB * LAT];    // x, fp16
__device__ unsigned g_max_bits;

// ---------------------------------------------------------------------------
// Helpers
// ---------------------------------------------------------------------------
__device__ __forceinline__ unsigned fenc(float f) {
    unsigned u = __float_as_uint(f);
    return (u & 0x80000000u) ? ~u : (u | 0x80000000u);
}
__device__ __forceinline__ float fdec(unsigned u) {
    unsigned b = (u & 0x80000000u) ? (u ^ 0x80000000u) : ~u;
    return __uint_as_float(b);
}
__device__ __forceinline__ uint32_t smem_u32(const void* p) {
    return (uint32_t)__cvta_generic_to_shared(p);
}
__device__ __forceinline__ void cpasync16(uint32_t dst, const void* src) {
    asm volatile("cp.async.cg.shared.global [%0], [%1], 16;" :: "r"(dst), "l"(src));
}
#define CP_COMMIT() asm volatile("cp.async.commit_group;" ::: "memory")
#define CP_WAIT2()  asm volatile("cp.async.wait_group 2;" ::: "memory")

__device__ __forceinline__ void ldsm4(uint32_t* r, uint32_t addr) {
    asm volatile("ldmatrix.sync.aligned.m8n8.x4.shared.b16 {%0,%1,%2,%3}, [%4];"
                 : "=r"(r[0]), "=r"(r[1]), "=r"(r[2]), "=r"(r[3]) : "r"(addr));
}
__device__ __forceinline__ void mma16816(float* c, const uint32_t* a, const uint32_t* b) {
    asm volatile("mma.sync.aligned.m16n8k16.row.col.f32.f16.f16.f32 "
                 "{%0,%1,%2,%3}, {%4,%5,%6,%7}, {%8,%9}, {%0,%1,%2,%3};"
                 : "+f"(c[0]), "+f"(c[1]), "+f"(c[2]), "+f"(c[3])
                 : "r"(a[0]), "r"(a[1]), "r"(a[2]), "r"(a[3]), "r"(b[0]), "r"(b[1]));
}

// smem tile geometry: 128 rows x 32 fp16 (64B) padded to 80B (conflict-free LDSM)
#define ROWB        80
#define TILE_B      (128 * ROWB)      // 10240
#define STAGE_B     (2 * TILE_B)      // 20480  (A, B)
#define NSTAGE      4
#define SMEM_BYTES  (NSTAGE * STAGE_B)   // 81920

// ---------------------------------------------------------------------------
// Prep kernels
// ---------------------------------------------------------------------------
__global__ void reset_max_kernel() { g_max_bits = 0u; }

// transpose to fp16: src [K][2048] f32 -> dst [2048][K1PAD] half (pad = 0)
__global__ void transpose_half_kernel(const float* __restrict__ src, int K, int which)
{
    __shared__ float t[32][33];
    __half* dst = which ? g_Ct : g_Wt;
    const int kb = blockIdx.y * 32;
    const int mb = blockIdx.x * 32;
    const int tx = threadIdx.x, ty = threadIdx.y;
#pragma unroll
    for (int r = ty; r < 32; r += 8) {
        const int k = kb + r;
        t[r][tx] = (k < K) ? src[(size_t)k * LAT + mb + tx] : 0.f;
    }
    __syncthreads();
#pragma unroll
    for (int r = ty; r < 32; r += 8)
        dst[(size_t)(mb + r) * K1PAD + kb + tx] = __float2half_rn(t[tx][r]);
}

__global__ void x_half_kernel(const float* __restrict__ x, int n2)
{
    const int i = blockIdx.x * blockDim.x + threadIdx.x;
    if (i < n2) {
        const float2 v = ((const float2*)x)[i];
        ((__half2*)g_x)[i] = __floats2half2_rn(v.x, v.y);
    }
}

// ---------------------------------------------------------------------------
// GEMM mainloop: acc[mt][nt][4] += sum_k A[arow][k] * B[brow][k]  (fp16, f32 acc)
// 256 threads, 8 warps as 2(m) x 4(n); warp tile 64x32. K-chunks of 32,
// 4-stage cp.async pipeline (prefetch depth 3).
// ---------------------------------------------------------------------------
__device__ __forceinline__ void gemm_main(
    const __half* __restrict__ A, const __half* __restrict__ B,
    int arow0, int brow0, int ldk, int nchunks,
    char* smem, float acc[4][4][4])
{
    const int tid = threadIdx.x;
    const int lane = tid & 31;
    const int w = tid >> 5;
    const int wm = w >> 2;            // 0..1
    const int wn = w & 3;             // 0..3
    const uint32_t sbase = smem_u32(smem);

#pragma unroll
    for (int mt = 0; mt < 4; mt++)
#pragma unroll
        for (int nt = 0; nt < 4; nt++)
#pragma unroll
            for (int q = 0; q < 4; q++) acc[mt][nt][q] = 0.f;

    // global->shared loader: thread covers 32B of one row of each tile
    const int lr = tid >> 1;                    // row 0..127
    const int lc0 = (tid & 1) * 2;              // 16B-chunk base (0 or 2)
    const __half* gA = A + (size_t)(arow0 + lr) * ldk;
    const __half* gB = B + (size_t)(brow0 + lr) * ldk;
    const uint32_t sdst0 = sbase + lr * ROWB + lc0 * 16;

    // ldmatrix lane offsets (within a tile)
    uint32_t aoff[2][4], boff[2][2];
#pragma unroll
    for (int ks = 0; ks < 2; ks++) {
#pragma unroll
        for (int mt = 0; mt < 4; mt++)
            aoff[ks][mt] = sbase + (uint32_t)((wm * 64 + mt * 16 + (lane & 15)) * ROWB
                                              + ks * 32 + (lane >> 4) * 16);
#pragma unroll
        for (int np = 0; np < 2; np++)
            boff[ks][np] = sbase + (uint32_t)((wn * 32 + np * 16 + (lane & 7) + (lane >> 4) * 8) * ROWB
                                              + ks * 32 + ((lane >> 3) & 1) * 16);
    }

#define LOAD_STAGE(c, s)                                                       \
    do {                                                                       \
        const size_t ke = (size_t)(c) * 32 + lc0 * 8;                          \
        const uint32_t d = sdst0 + (s) * STAGE_B;                              \
        const char* pa = (const char*)(gA + ke);                               \
        const char* pb = (const char*)(gB + ke);                               \
        cpasync16(d, pa);               cpasync16(d + 16, pa + 16);            \
        cpasync16(d + TILE_B, pb);      cpasync16(d + TILE_B + 16, pb + 16);   \
    } while (0)

    LOAD_STAGE(0, 0); CP_COMMIT();
    LOAD_STAGE(1, 1); CP_COMMIT();
    LOAD_STAGE(2, 2); CP_COMMIT();

    uint32_t a[2][4][4], b[2][2][4];

    for (int c = 0; c < nchunks; ++c) {
        const int s = c & 3;
        CP_WAIT2();
        __syncthreads();
        const int nc = c + 3;
        if (nc < nchunks) LOAD_STAGE(nc, nc & 3);
        CP_COMMIT();

        const uint32_t so = (uint32_t)(s * STAGE_B);
#pragma unroll
        for (int ks = 0; ks < 2; ks++)
#pragma unroll
            for (int mt = 0; mt < 4; mt++)
                ldsm4(a[ks][mt], aoff[ks][mt] + so);
#pragma unroll
        for (int ks = 0; ks < 2; ks++)
#pragma unroll
            for (int np = 0; np < 2; np++)
                ldsm4(b[ks][np], boff[ks][np] + so + TILE_B);
#pragma unroll
        for (int ks = 0; ks < 2; ks++)
#pragma unroll
            for (int mt = 0; mt < 4; mt++)
#pragma unroll
                for (int np = 0; np < 2; np++) {
                    mma16816(acc[mt][np * 2 + 0], a[ks][mt], &b[ks][np][0]);
                    mma16816(acc[mt][np * 2 + 1], a[ks][mt], &b[ks][np][2]);
                }
    }
#undef LOAD_STAGE
}

// ---------------------------------------------------------------------------
// GEMM1: Mt[n][m] = sum_k Ct[n][k] * Wt[m][k]; epilogue rounds to fp16.
// ---------------------------------------------------------------------------
__global__ __launch_bounds__(256, 1) void gemm1_tc()
{
    extern __shared__ __align__(128) char smem[];
    float acc[4][4][4];
    gemm_main(g_Ct, g_Wt, blockIdx.y * 128, blockIdx.x * 128, K1PAD, K1PAD / 32,
              smem, acc);

    const int lane = threadIdx.x & 31;
    const int w = threadIdx.x >> 5;
    const int r0 = blockIdx.y * 128 + (w >> 2) * 64;
    const int c0 = blockIdx.x * 128 + (w & 3) * 32;

#pragma unroll
    for (int mt = 0; mt < 4; mt++) {
#pragma unroll
        for (int nt = 0; nt < 4; nt++) {
            const int col = c0 + nt * 8 + (lane & 3) * 2;
            const float* cc = acc[mt][nt];
#pragma unroll
            for (int h = 0; h < 2; h++) {
                const int r = r0 + mt * 16 + (lane >> 2) + h * 8;
                *(__half2*)(g_Mt + (size_t)r * LAT + col) =
                    __floats2half2_rn(cc[2 * h + 0], cc[2 * h + 1]);
            }
        }
    }
}

// ---------------------------------------------------------------------------
// GEMM2: out[b][n] = sum_m x[b][m] * Mt[n][m]; fused global max.
// ---------------------------------------------------------------------------
__global__ __launch_bounds__(256, 1) void gemm2_tc(float* __restrict__ out)
{
    extern __shared__ __align__(128) char smem[];
    float acc[4][4][4];
    gemm_main(g_x, g_Mt, blockIdx.y * 128, blockIdx.x * 128, LAT, LAT / 32,
              smem, acc);

    const int lane = threadIdx.x & 31;
    const int w = threadIdx.x >> 5;
    const int r0 = blockIdx.y * 128 + (w >> 2) * 64;
    const int c0 = blockIdx.x * 128 + (w & 3) * 32;

    float lmax = -3.402823466e+38f;
#pragma unroll
    for (int mt = 0; mt < 4; mt++) {
#pragma unroll
        for (int nt = 0; nt < 4; nt++) {
            const int col = c0 + nt * 8 + (lane & 3) * 2;
            const float* cc = acc[mt][nt];
#pragma unroll
            for (int h = 0; h < 2; h++) {
                const int r = r0 + mt * 16 + (lane >> 2) + h * 8;
                float2 v = make_float2(cc[2 * h + 0], cc[2 * h + 1]);
                lmax = fmaxf(lmax, fmaxf(v.x, v.y));
                *(float2*)(out + (size_t)r * LAT + col) = v;
            }
        }
    }

#pragma unroll
    for (int o = 16; o > 0; o >>= 1)
        lmax = fmaxf(lmax, __shfl_xor_sync(0xFFFFFFFFu, lmax, o));
    __shared__ float wmax[8];
    if (lane == 0) wmax[w] = lmax;
    __syncthreads();
    if (threadIdx.x == 0) {
        float m = wmax[0];
#pragma unroll
        for (int i = 1; i < 8; i++) m = fmaxf(m, wmax[i]);
        atomicMax(&g_max_bits, fenc(m));
    }
}

// ---------------------------------------------------------------------------
// out *= 1/max
// ---------------------------------------------------------------------------
__global__ void scale_kernel(float* __restrict__ out, int n4)
{
    const float inv = 1.0f / fdec(g_max_bits);
    const int i = blockIdx.x * blockDim.x + threadIdx.x;
    if (i < n4) {
        float4 v = ((float4*)out)[i];
        v.x *= inv; v.y *= inv; v.z *= inv; v.w *= inv;
        ((float4*)out)[i] = v;
    }
}

// ---------------------------------------------------------------------------
extern "C" void kernel_launch(void* const* d_in, const int* in_sizes, int n_in,
                              void* d_out, int out_size)
{
    const float* x = (const float*)d_in[0];   // (B, 2048)
    const float* W = (const float*)d_in[1];   // (NF, 2048)
    const float* C = (const float*)d_in[2];   // (NF, 2048)
    float* out = (float*)d_out;

    const int B  = in_sizes[0] / LAT;         // 4096
    const int NF = in_sizes[1] / LAT;         // 2074

    cudaFuncSetAttribute(gemm1_tc, cudaFuncAttributeMaxDynamicSharedMemorySize, SMEM_BYTES);
    cudaFuncSetAttribute(gemm2_tc, cudaFuncAttributeMaxDynamicSharedMemorySize, SMEM_BYTES);

    reset_max_kernel<<<1, 1>>>();

    dim3 tb(32, 8);
    transpose_half_kernel<<<dim3(LAT / 32, K1PAD / 32), tb>>>(W, NF, 0);
    transpose_half_kernel<<<dim3(LAT / 32, K1PAD / 32), tb>>>(C, NF, 1);
    const int n2 = B * LAT / 2;
    x_half_kernel<<<(n2 + 255) / 256, 256>>>(x, n2);

    // GEMM1: Mt = (W^T C)^T   (2048x2048, K = K1PAD)
    gemm1_tc<<<dim3(LAT / 128, LAT / 128), 256, SMEM_BYTES>>>();

    // GEMM2: out = x @ M + fused global max
    gemm2_tc<<<dim3(LAT / 128, B / 128), 256, SMEM_BYTES>>>(out);

    const int n4 = out_size / 4;
    scale_kernel<<<(n4 + 255) / 256, 256>>>(out, n4);
}